// round 3
// baseline (speedup 1.0000x reference)
#include <cuda_runtime.h>

// Problem constants
#define BATCH 128
#define CIN   9
#define T0    2048
#define T1    1024
#define RR    512          // reduced timesteps per sample
#define NNODES 65536       // BATCH * RR
#define ESING 8192         // edges of the per-sample graph (first 8192 of edge_index)
#define HID   128
#define OUTF  12

// ---------------- scratch (device globals; no allocations allowed) ----------
__device__ float g_tc1[BATCH * 16 * T1];    // after conv1+relu+pool  [B,16,1024]
__device__ float g_nodes[NNODES * 32];      // after conv2+relu+pool, node-major [N,32]
__device__ float g_xa[NNODES * 32];         // A_norm @ X
__device__ float g_h1[NNODES * HID];        // relu(Xa @ W1 + b1)
__device__ float g_h1a[NNODES * HID];       // A_norm @ H1
__device__ float g_h2[NNODES * HID];        // relu(H1a @ W2 + b2)
__device__ float g_meanv[BATCH * HID];

// per-sample graph CSR (by target node)
__device__ int   g_cnt[RR];
__device__ int   g_pos[RR];
__device__ int   g_ptr[RR + 1];
__device__ int   g_src[ESING + RR];
__device__ float g_wgt[ESING + RR];
__device__ float g_dis[RR];

// ---------------- graph build ----------------
__global__ void k_zero() {
    int t = threadIdx.x;
    g_cnt[t] = 0;
    g_pos[t] = 0;
}

__global__ void k_count(const int* __restrict__ ei, int etot) {
    int e = blockIdx.x * 256 + threadIdx.x;
    if (e < ESING) atomicAdd(&g_cnt[ei[etot + e]], 1);
}

__global__ void k_scan() {
    __shared__ int s[RR];
    int t = threadIdx.x;
    int v = g_cnt[t] + 1;               // +1 self loop
    s[t] = v;
    g_dis[t] = rsqrtf((float)v);
    __syncthreads();
    for (int off = 1; off < RR; off <<= 1) {
        int tmp = (t >= off) ? s[t - off] : 0;
        __syncthreads();
        s[t] += tmp;
        __syncthreads();
    }
    g_ptr[t + 1] = s[t];
    if (t == 0) g_ptr[0] = 0;
}

__global__ void k_fill(const int* __restrict__ ei, int etot) {
    int e = blockIdx.x * 256 + threadIdx.x;
    if (e < ESING) {
        int s = ei[e];
        int t = ei[etot + e];
        int k = atomicAdd(&g_pos[t], 1);
        int idx = g_ptr[t] + k;
        g_src[idx] = s;
        g_wgt[idx] = g_dis[s] * g_dis[t];
    }
}

__global__ void k_self() {
    int t = threadIdx.x;
    int idx = g_ptr[t] + g_cnt[t];
    g_src[idx] = t;
    float d = g_dis[t];
    g_wgt[idx] = d * d;
}

// ---------------- temporal convs (conv + relu + maxpool2 fused) -------------
__global__ void k_conv1(const float* __restrict__ x, const float* __restrict__ w,
                        const float* __restrict__ bias) {
    int p  = blockIdx.x * 128 + threadIdx.x;   // pooled pos 0..1023
    int oc = blockIdx.y;
    int b  = blockIdx.z;
    __shared__ float sw[CIN * 5];
    if (threadIdx.x < CIN * 5) sw[threadIdx.x] = w[oc * CIN * 5 + threadIdx.x];
    __syncthreads();
    float bv = bias[oc];
    float a0 = bv, a1 = bv;
    const float* xb = x + (long)b * CIN * T0;
    int t = 2 * p;
#pragma unroll
    for (int c = 0; c < CIN; c++) {
        const float* xc = xb + c * T0;
        float v[6];
#pragma unroll
        for (int j = 0; j < 6; j++) {
            int i = t - 2 + j;
            v[j] = (i >= 0 && i < T0) ? xc[i] : 0.f;
        }
#pragma unroll
        for (int k = 0; k < 5; k++) {
            float wv = sw[c * 5 + k];
            a0 = fmaf(v[k],     wv, a0);
            a1 = fmaf(v[k + 1], wv, a1);
        }
    }
    g_tc1[((long)b * 16 + oc) * T1 + p] = fmaxf(fmaxf(a0, a1), 0.f);
}

__global__ void k_conv2(const float* __restrict__ w, const float* __restrict__ bias) {
    int p  = blockIdx.x * 128 + threadIdx.x;   // pooled pos 0..511
    int oc = blockIdx.y;
    int b  = blockIdx.z;
    __shared__ float sw[16 * 5];
    if (threadIdx.x < 16 * 5) sw[threadIdx.x] = w[oc * 16 * 5 + threadIdx.x];
    __syncthreads();
    float bv = bias[oc];
    float a0 = bv, a1 = bv;
    const float* hb = g_tc1 + (long)b * 16 * T1;
    int t = 2 * p;
#pragma unroll
    for (int c = 0; c < 16; c++) {
        const float* hc = hb + c * T1;
        float v[6];
#pragma unroll
        for (int j = 0; j < 6; j++) {
            int i = t - 2 + j;
            v[j] = (i >= 0 && i < T1) ? hc[i] : 0.f;
        }
#pragma unroll
        for (int k = 0; k < 5; k++) {
            float wv = sw[c * 5 + k];
            a0 = fmaf(v[k],     wv, a0);
            a1 = fmaf(v[k + 1], wv, a1);
        }
    }
    g_nodes[((long)b * RR + p) * 32 + oc] = fmaxf(fmaxf(a0, a1), 0.f);
}

// ---------------- sparse aggregations (shared per-sample CSR) ---------------
__global__ void k_agg32() {   // g_nodes -> g_xa, F=32, 4 nodes / 128-thr block
    int tid = threadIdx.x;
    int node = blockIdx.x * 4 + (tid >> 5);
    int f = tid & 31;
    int b = node >> 9;          // /RR
    int t = node & (RR - 1);
    const float* inb = g_nodes + (long)b * RR * 32;
    int beg = g_ptr[t], end = g_ptr[t + 1];
    float acc = 0.f;
    for (int i = beg; i < end; i++)
        acc = fmaf(g_wgt[i], inb[g_src[i] * 32 + f], acc);
    g_xa[(long)node * 32 + f] = acc;
}

__global__ void k_agg128() {  // g_h1 -> g_h1a, F=128, 2 nodes / 256-thr block
    int tid = threadIdx.x;
    int node = blockIdx.x * 2 + (tid >> 7);
    int f = tid & 127;
    int b = node >> 9;
    int t = node & (RR - 1);
    const float* inb = g_h1 + (long)b * RR * HID;
    int beg = g_ptr[t], end = g_ptr[t + 1];
    float acc = 0.f;
    for (int i = beg; i < end; i++)
        acc = fmaf(g_wgt[i], inb[g_src[i] * HID + f], acc);
    g_h1a[(long)node * HID + f] = acc;
}

// ---------------- GEMM1: [N,32]@[32,128] + bias, relu -----------------------
__global__ void k_gemm1(const float* __restrict__ W, const float* __restrict__ bias) {
    __shared__ float as[64][33];
    __shared__ float ws[32][128];
    int tid = threadIdx.x;
    long rowBase = (long)blockIdx.x * 64;
    for (int id = tid; id < 64 * 32; id += 256) {
        int r = id >> 5, k = id & 31;
        as[r][k] = g_xa[(rowBase + r) * 32 + k];
    }
    for (int id = tid; id < 32 * 128; id += 256)
        ws[id >> 7][id & 127] = W[id];
    __syncthreads();
    int rg = tid >> 4;     // 16 row groups, 4 rows each
    int cg = tid & 15;     // 16 col lanes, cols cg + 16*j
    int row0 = rg * 4;
    float acc[4][8];
#pragma unroll
    for (int i = 0; i < 4; i++)
#pragma unroll
        for (int j = 0; j < 8; j++) acc[i][j] = 0.f;
#pragma unroll
    for (int k = 0; k < 32; k++) {
        float a[4], bb[8];
#pragma unroll
        for (int i = 0; i < 4; i++) a[i] = as[row0 + i][k];
#pragma unroll
        for (int j = 0; j < 8; j++) bb[j] = ws[k][cg + 16 * j];
#pragma unroll
        for (int i = 0; i < 4; i++)
#pragma unroll
            for (int j = 0; j < 8; j++) acc[i][j] = fmaf(a[i], bb[j], acc[i][j]);
    }
#pragma unroll
    for (int i = 0; i < 4; i++)
#pragma unroll
        for (int j = 0; j < 8; j++) {
            int col = cg + 16 * j;
            g_h1[(rowBase + row0 + i) * HID + col] =
                fmaxf(acc[i][j] + bias[col], 0.f);
        }
}

// ---------------- GEMM2: [N,128]@[128,128] + bias, relu ---------------------
__global__ void k_gemm2(const float* __restrict__ W, const float* __restrict__ bias) {
    __shared__ float as[128][33];
    __shared__ float ws[32][128];
    int tid = threadIdx.x;
    long rowBase = (long)blockIdx.x * 128;
    int rg = tid >> 4;     // 16 row groups, 8 rows each
    int cg = tid & 15;     // cols cg + 16*j
    int row0 = rg * 8;
    float acc[8][8];
#pragma unroll
    for (int i = 0; i < 8; i++)
#pragma unroll
        for (int j = 0; j < 8; j++) acc[i][j] = 0.f;
    for (int kc = 0; kc < 4; kc++) {
        __syncthreads();
        for (int id = tid; id < 128 * 32; id += 256) {
            int r = id >> 5, k = id & 31;
            as[r][k] = g_h1a[(rowBase + r) * HID + kc * 32 + k];
        }
        for (int id = tid; id < 32 * 128; id += 256) {
            int kk = id >> 7, c = id & 127;
            ws[kk][c] = W[(kc * 32 + kk) * HID + c];
        }
        __syncthreads();
#pragma unroll
        for (int k = 0; k < 32; k++) {
            float a[8], bb[8];
#pragma unroll
            for (int i = 0; i < 8; i++) a[i] = as[row0 + i][k];
#pragma unroll
            for (int j = 0; j < 8; j++) bb[j] = ws[k][cg + 16 * j];
#pragma unroll
            for (int i = 0; i < 8; i++)
#pragma unroll
                for (int j = 0; j < 8; j++) acc[i][j] = fmaf(a[i], bb[j], acc[i][j]);
        }
    }
#pragma unroll
    for (int i = 0; i < 8; i++)
#pragma unroll
        for (int j = 0; j < 8; j++) {
            int col = cg + 16 * j;
            g_h2[(rowBase + row0 + i) * HID + col] =
                fmaxf(acc[i][j] + bias[col], 0.f);
        }
}

// ---------------- mean over R, then fc --------------------------------------
__global__ void k_mean() {
    int b = blockIdx.x, f = threadIdx.x;
    const float* p = g_h2 + (long)b * RR * HID + f;
    float acc = 0.f;
    for (int r = 0; r < RR; r++) acc += p[(long)r * HID];
    g_meanv[b * HID + f] = acc * (1.0f / RR);
}

__global__ void k_fc(const float* __restrict__ fw, const float* __restrict__ fb,
                     float* __restrict__ out) {
    int b = blockIdx.x;
    __shared__ float m[HID];
    m[threadIdx.x] = g_meanv[b * HID + threadIdx.x];
    __syncthreads();
    if (threadIdx.x < OUTF) {
        float acc = fb[threadIdx.x];
#pragma unroll
        for (int f = 0; f < HID; f++) acc = fmaf(m[f], fw[f * OUTF + threadIdx.x], acc);
        out[b * OUTF + threadIdx.x] = acc;
    }
}

// ---------------- launch -----------------------------------------------------
extern "C" void kernel_launch(void* const* d_in, const int* in_sizes, int n_in,
                              void* d_out, int out_size) {
    const float* x   = (const float*)d_in[0];
    const int*   ei  = (const int*)  d_in[1];
    const float* c1w = (const float*)d_in[2];
    const float* c1b = (const float*)d_in[3];
    const float* c2w = (const float*)d_in[4];
    const float* c2b = (const float*)d_in[5];
    const float* g1w = (const float*)d_in[6];
    const float* g1b = (const float*)d_in[7];
    const float* g2w = (const float*)d_in[8];
    const float* g2b = (const float*)d_in[9];
    const float* fw  = (const float*)d_in[10];
    const float* fb  = (const float*)d_in[11];
    float* out = (float*)d_out;
    int etot = in_sizes[1] / 2;

    // graph build (cheap, every launch; deterministic up to fp tolerance)
    k_zero<<<1, RR>>>();
    k_count<<<ESING / 256, 256>>>(ei, etot);
    k_scan<<<1, RR>>>();
    k_fill<<<ESING / 256, 256>>>(ei, etot);
    k_self<<<1, RR>>>();

    // temporal convs
    k_conv1<<<dim3(T1 / 128, 16, BATCH), 128>>>(x, c1w, c1b);
    k_conv2<<<dim3(RR / 128, 32, BATCH), 128>>>(c2w, c2b);

    // GCN1: aggregate in 32-dim first, then GEMM with fused bias+relu
    k_agg32<<<NNODES / 4, 128>>>();
    k_gemm1<<<NNODES / 64, 256>>>(g1w, g1b);

    // GCN2: aggregate in 128-dim, then GEMM with fused bias+relu
    k_agg128<<<NNODES / 2, 256>>>();
    k_gemm2<<<NNODES / 128, 256>>>(g2w, g2b);

    // readout
    k_mean<<<BATCH, HID>>>();
    k_fc<<<BATCH, HID>>>(fw, fb, out);
}

// round 4
// speedup vs baseline: 1.2978x; 1.2978x over previous
#include <cuda_runtime.h>

#define BATCH 128
#define CIN   9
#define T0    2048
#define T1    1024
#define RR    512
#define NNODES 65536
#define ESING 8192
#define HID   128
#define OUTF  12

// ---------------- scratch ----------------------------------------------------
__device__ __align__(16) float g_tc1[BATCH * 16 * T1];
__device__ __align__(16) float g_nodes[NNODES * 32];
__device__ __align__(16) float g_h1[NNODES * HID];
__device__ __align__(16) float g_h1a[NNODES * HID];
__device__ float g_meanv[BATCH * HID];

__device__ int   g_ptr[RR + 1];
__device__ int   g_src[ESING + RR];
__device__ float g_wgt[ESING + RR];

// ---------------- fused graph build (1 block) --------------------------------
__global__ void k_graph(const int* __restrict__ ei, int etot) {
    __shared__ int   s_cnt[RR];
    __shared__ int   s_pos[RR];
    __shared__ int   s_ptr[RR + 1];
    __shared__ int   s_scan[RR];
    __shared__ float s_dis[RR];
    int t = threadIdx.x;
    s_cnt[t] = 0;
    s_pos[t] = 0;
    for (int i = t; i < BATCH * HID; i += RR) g_meanv[i] = 0.f;   // zero mean accumulator
    __syncthreads();
    for (int e = t; e < ESING; e += RR) atomicAdd(&s_cnt[ei[etot + e]], 1);
    __syncthreads();
    int deg = s_cnt[t] + 1;                 // + self loop
    s_dis[t]  = rsqrtf((float)deg);
    s_scan[t] = deg;
    __syncthreads();
    for (int off = 1; off < RR; off <<= 1) {
        int v = (t >= off) ? s_scan[t - off] : 0;
        __syncthreads();
        s_scan[t] += v;
        __syncthreads();
    }
    s_ptr[t + 1] = s_scan[t];
    if (t == 0) s_ptr[0] = 0;
    __syncthreads();
    g_ptr[t + 1] = s_ptr[t + 1];
    if (t == 0) g_ptr[0] = 0;
    for (int e = t; e < ESING; e += RR) {
        int s = ei[e], tt = ei[etot + e];
        int k = atomicAdd(&s_pos[tt], 1);
        int idx = s_ptr[tt] + k;
        g_src[idx] = s;
        g_wgt[idx] = s_dis[s] * s_dis[tt];
    }
    // self loop at fixed slot (independent of atomic ordering)
    int idx = s_ptr[t] + s_cnt[t];
    g_src[idx] = t;
    g_wgt[idx] = s_dis[t] * s_dis[t];
}

// ---------------- conv1: 8 ocs x 2 pooled positions per thread ----------------
__global__ void k_conv1(const float* __restrict__ x, const float* __restrict__ w,
                        const float* __restrict__ bias) {
    __shared__ float sx[CIN][516];
    __shared__ float sw[8][CIN][5];
    __shared__ float sb[8];
    int tid = threadIdx.x;
    int P0  = blockIdx.x * 256;         // pooled base (256 per block)
    int og  = blockIdx.y;               // oc group 0..1
    int b   = blockIdx.z;
    int raw0 = 2 * P0 - 2;
    const float* xb = x + (long)b * CIN * T0;
    for (int id = tid; id < CIN * 516; id += 128) {
        int c = id / 516, i = id - c * 516;
        int ti = raw0 + i;
        sx[c][i] = (ti >= 0 && ti < T0) ? xb[c * T0 + ti] : 0.f;
    }
    for (int id = tid; id < 8 * CIN * 5; id += 128)
        ((float*)sw)[id] = w[og * 8 * CIN * 5 + id];
    if (tid < 8) sb[tid] = bias[og * 8 + tid];
    __syncthreads();

    float r[8][4];
#pragma unroll
    for (int q = 0; q < 8; q++) {
        float bv = sb[q];
#pragma unroll
        for (int j = 0; j < 4; j++) r[q][j] = bv;
    }
#pragma unroll
    for (int c = 0; c < CIN; c++) {
        float v[8];
#pragma unroll
        for (int j = 0; j < 8; j++) v[j] = sx[c][4 * tid + j];
#pragma unroll
        for (int q = 0; q < 8; q++) {
#pragma unroll
            for (int k = 0; k < 5; k++) {
                float wv = sw[q][c][k];
                r[q][0] = fmaf(v[k],     wv, r[q][0]);
                r[q][1] = fmaf(v[k + 1], wv, r[q][1]);
                r[q][2] = fmaf(v[k + 2], wv, r[q][2]);
                r[q][3] = fmaf(v[k + 3], wv, r[q][3]);
            }
        }
    }
    int p0 = P0 + 2 * tid;
#pragma unroll
    for (int q = 0; q < 8; q++) {
        int oc = og * 8 + q;
        float o0 = fmaxf(fmaxf(r[q][0], r[q][1]), 0.f);
        float o1 = fmaxf(fmaxf(r[q][2], r[q][3]), 0.f);
        *(float2*)&g_tc1[((long)b * 16 + oc) * T1 + p0] = make_float2(o0, o1);
    }
}

// ---------------- conv2: 8 ocs x 2 pooled positions per thread ----------------
__global__ void k_conv2(const float* __restrict__ w, const float* __restrict__ bias) {
    __shared__ float sx[16][516];
    __shared__ float sw[8][16][5];
    __shared__ float sb[8];
    int tid = threadIdx.x;
    int P0  = blockIdx.x * 256;         // pooled base 0..511
    int og  = blockIdx.y;               // oc group 0..3
    int b   = blockIdx.z;
    int raw0 = 2 * P0 - 2;
    const float* hb = g_tc1 + (long)b * 16 * T1;
    for (int id = tid; id < 16 * 516; id += 128) {
        int c = id / 516, i = id - c * 516;
        int ti = raw0 + i;
        sx[c][i] = (ti >= 0 && ti < T1) ? hb[c * T1 + ti] : 0.f;
    }
    for (int id = tid; id < 8 * 16 * 5; id += 128)
        ((float*)sw)[id] = w[og * 8 * 16 * 5 + id];
    if (tid < 8) sb[tid] = bias[og * 8 + tid];
    __syncthreads();

    float r[8][4];
#pragma unroll
    for (int q = 0; q < 8; q++) {
        float bv = sb[q];
#pragma unroll
        for (int j = 0; j < 4; j++) r[q][j] = bv;
    }
#pragma unroll
    for (int c = 0; c < 16; c++) {
        float v[8];
#pragma unroll
        for (int j = 0; j < 8; j++) v[j] = sx[c][4 * tid + j];
#pragma unroll
        for (int q = 0; q < 8; q++) {
#pragma unroll
            for (int k = 0; k < 5; k++) {
                float wv = sw[q][c][k];
                r[q][0] = fmaf(v[k],     wv, r[q][0]);
                r[q][1] = fmaf(v[k + 1], wv, r[q][1]);
                r[q][2] = fmaf(v[k + 2], wv, r[q][2]);
                r[q][3] = fmaf(v[k + 3], wv, r[q][3]);
            }
        }
    }
    int p0 = P0 + 2 * tid;
    long node0 = (long)b * RR + p0;
    float4 o0a, o0b, o1a, o1b;
    float* o0 = (float*)&o0a;  // [8] via two float4
    float* o1 = (float*)&o1a;
    float out0[8], out1[8];
#pragma unroll
    for (int q = 0; q < 8; q++) {
        out0[q] = fmaxf(fmaxf(r[q][0], r[q][1]), 0.f);
        out1[q] = fmaxf(fmaxf(r[q][2], r[q][3]), 0.f);
    }
    (void)o0; (void)o1; (void)o0b; (void)o1b;
    float4* d0 = (float4*)&g_nodes[node0 * 32 + og * 8];
    float4* d1 = (float4*)&g_nodes[(node0 + 1) * 32 + og * 8];
    d0[0] = make_float4(out0[0], out0[1], out0[2], out0[3]);
    d0[1] = make_float4(out0[4], out0[5], out0[6], out0[7]);
    d1[0] = make_float4(out1[0], out1[1], out1[2], out1[3]);
    d1[1] = make_float4(out1[4], out1[5], out1[6], out1[7]);
}

// ---------------- fused agg32 + GEMM1 ([N,32]@[32,128] + bias, relu) ----------
__global__ void k_gemm1f(const float* __restrict__ W, const float* __restrict__ bias) {
    __shared__ float as[64][33];
    __shared__ float ws[32][128];
    int tid = threadIdx.x;
    long rowBase = (long)blockIdx.x * 64;
    int b = (int)(rowBase >> 9);
    const float* inb = g_nodes + (long)b * RR * 32;

    // aggregation straight into the A tile: warp per 8 rows, lane = feature
    int warp = tid >> 5, lane = tid & 31;
#pragma unroll
    for (int r8 = 0; r8 < 8; r8++) {
        int r = warp * 8 + r8;
        int t = (int)((rowBase + r) & (RR - 1));
        int beg = g_ptr[t], end = g_ptr[t + 1];
        float acc = 0.f;
        for (int i = beg; i < end; i++)
            acc = fmaf(g_wgt[i], inb[g_src[i] * 32 + lane], acc);
        as[r][lane] = acc;
    }
    for (int id = tid; id < 32 * 128; id += 256)
        ws[id >> 7][id & 127] = W[id];
    __syncthreads();

    int rg = tid >> 4, cg = tid & 15, row0 = rg * 4;
    float acc[4][8];
#pragma unroll
    for (int i = 0; i < 4; i++)
#pragma unroll
        for (int j = 0; j < 8; j++) acc[i][j] = 0.f;
#pragma unroll
    for (int k = 0; k < 32; k++) {
        float a[4], bb[8];
#pragma unroll
        for (int i = 0; i < 4; i++) a[i] = as[row0 + i][k];
#pragma unroll
        for (int j = 0; j < 8; j++) bb[j] = ws[k][cg + 16 * j];
#pragma unroll
        for (int i = 0; i < 4; i++)
#pragma unroll
            for (int j = 0; j < 8; j++) acc[i][j] = fmaf(a[i], bb[j], acc[i][j]);
    }
#pragma unroll
    for (int i = 0; i < 4; i++)
#pragma unroll
        for (int j = 0; j < 8; j++) {
            int col = cg + 16 * j;
            g_h1[(rowBase + row0 + i) * HID + col] = fmaxf(acc[i][j] + bias[col], 0.f);
        }
}

// ---------------- agg128 with float4 gathers ---------------------------------
__global__ void k_agg128() {
    int tid = threadIdx.x;
    int nl = tid >> 5;                  // 8 nodes per 256-thread block
    int lane = tid & 31;                // 4 features each
    long node = (long)blockIdx.x * 8 + nl;
    int b = (int)(node >> 9);
    int t = (int)(node & (RR - 1));
    const float4* inb = (const float4*)(g_h1 + (long)b * RR * HID);
    int beg = g_ptr[t], end = g_ptr[t + 1];
    float4 acc = make_float4(0.f, 0.f, 0.f, 0.f);
    for (int i = beg; i < end; i++) {
        float w = g_wgt[i];
        float4 v = inb[(long)g_src[i] * 32 + lane];
        acc.x = fmaf(w, v.x, acc.x);
        acc.y = fmaf(w, v.y, acc.y);
        acc.z = fmaf(w, v.z, acc.z);
        acc.w = fmaf(w, v.w, acc.w);
    }
    ((float4*)g_h1a)[node * 32 + lane] = acc;
}

// ---------------- GEMM2 + bias + relu + mean (no h2 materialization) ---------
__global__ void k_gemm2m(const float* __restrict__ W, const float* __restrict__ bias) {
    __shared__ float as[128][33];
    __shared__ float ws[32][128];
    __shared__ float smean[HID];
    int tid = threadIdx.x;
    long rowBase = (long)blockIdx.x * 128;
    int b = blockIdx.x >> 2;            // 4 blocks per sample
    int rg = tid >> 4, cg = tid & 15, row0 = rg * 8;
    float acc[8][8];
#pragma unroll
    for (int i = 0; i < 8; i++)
#pragma unroll
        for (int j = 0; j < 8; j++) acc[i][j] = 0.f;
    for (int kc = 0; kc < 4; kc++) {
        __syncthreads();
        for (int id = tid; id < 128 * 32; id += 256) {
            int r = id >> 5, k = id & 31;
            as[r][k] = g_h1a[(rowBase + r) * HID + kc * 32 + k];
        }
        for (int id = tid; id < 32 * 128; id += 256) {
            int kk = id >> 7, c = id & 127;
            ws[kk][c] = W[(kc * 32 + kk) * HID + c];
        }
        __syncthreads();
#pragma unroll
        for (int k = 0; k < 32; k++) {
            float a[8], bb[8];
#pragma unroll
            for (int i = 0; i < 8; i++) a[i] = as[row0 + i][k];
#pragma unroll
            for (int j = 0; j < 8; j++) bb[j] = ws[k][cg + 16 * j];
#pragma unroll
            for (int i = 0; i < 8; i++)
#pragma unroll
                for (int j = 0; j < 8; j++) acc[i][j] = fmaf(a[i], bb[j], acc[i][j]);
        }
    }
    if (tid < HID) smean[tid] = 0.f;
    __syncthreads();
#pragma unroll
    for (int j = 0; j < 8; j++) {
        int col = cg + 16 * j;
        float bv = bias[col];
        float s = 0.f;
#pragma unroll
        for (int i = 0; i < 8; i++) s += fmaxf(acc[i][j] + bv, 0.f);
        atomicAdd(&smean[col], s);
    }
    __syncthreads();
    if (tid < HID) atomicAdd(&g_meanv[b * HID + tid], smean[tid] * (1.0f / RR));
}

// ---------------- fc ---------------------------------------------------------
__global__ void k_fc(const float* __restrict__ fw, const float* __restrict__ fb,
                     float* __restrict__ out) {
    int b = blockIdx.x;
    __shared__ float m[HID];
    m[threadIdx.x] = g_meanv[b * HID + threadIdx.x];
    __syncthreads();
    if (threadIdx.x < OUTF) {
        float acc = fb[threadIdx.x];
#pragma unroll
        for (int f = 0; f < HID; f++)
            acc = fmaf(m[f], fw[f * OUTF + threadIdx.x], acc);
        out[b * OUTF + threadIdx.x] = acc;
    }
}

// ---------------- launch ------------------------------------------------------
extern "C" void kernel_launch(void* const* d_in, const int* in_sizes, int n_in,
                              void* d_out, int out_size) {
    const float* x   = (const float*)d_in[0];
    const int*   ei  = (const int*)  d_in[1];
    const float* c1w = (const float*)d_in[2];
    const float* c1b = (const float*)d_in[3];
    const float* c2w = (const float*)d_in[4];
    const float* c2b = (const float*)d_in[5];
    const float* g1w = (const float*)d_in[6];
    const float* g1b = (const float*)d_in[7];
    const float* g2w = (const float*)d_in[8];
    const float* g2b = (const float*)d_in[9];
    const float* fw  = (const float*)d_in[10];
    const float* fb  = (const float*)d_in[11];
    float* out = (float*)d_out;
    int etot = in_sizes[1] / 2;

    k_graph<<<1, RR>>>(ei, etot);                         // 1
    k_conv1<<<dim3(T1 / 256, 2, BATCH), 128>>>(x, c1w, c1b);   // 2
    k_conv2<<<dim3(RR / 256, 4, BATCH), 128>>>(c2w, c2b);      // 3
    k_gemm1f<<<NNODES / 64, 256>>>(g1w, g1b);             // 4
    k_agg128<<<NNODES / 8, 256>>>();                      // 5
    k_gemm2m<<<NNODES / 128, 256>>>(g2w, g2b);            // 6  (profiled by -s 5)
    k_fc<<<BATCH, HID>>>(fw, fb, out);                    // 7
}